// round 6
// baseline (speedup 1.0000x reference)
#include <cuda_runtime.h>
#include <cuda_bf16.h>

// ---------------------------------------------------------------------------
// Static problem shape
// ---------------------------------------------------------------------------
#define NE      100000
#define NNODES  10000
#define HEADS   8
#define XDIM    576
#define MT      128                       // edges per CTA
#define NGRID   ((NE + MT - 1) / MT)      // 782
#define THREADS 512
#define NSTEP   58

#define BSTR    144                       // B bf16 tile row stride (bytes)
#define RSTR    72                        // raw A row stride (floats) = 288B
// smem: 3 buffers, each: B(hi 18432 + lo 18432) then raw A (36864)
#define OFF_RAW 36864u
#define BUFSZ   73728u
#define SMEM_TOTAL (3 * 73728)            // 221184

typedef unsigned int u32;

// ---------------------------------------------------------------------------
// SO(2) path tables (validated rounds 1-5)
// ---------------------------------------------------------------------------
__constant__ int   c_i[29] = {0,2,6,  3,1,7,5,  0,2,6,  3,7,1,5,  8,4,
                              3,1,7,5,  0,2,6,  3,7,1,5,  8,4};
__constant__ int   c_w[29] = {0,3,6,  10,9,14,13,  1,4,7,  9,13,10,14,  18,17,
                              12,11,16,15,  2,5,8,  11,15,12,16,  17,18};
__constant__ float c_sgn[29] = {1,1,1,  1,1,1,1,  1,1,1,  1,1,-1,-1,  1,1,
                                1,1,1,1,  1,1,1,  1,1,-1,-1,  1,-1};

__constant__ unsigned char stt[NSTEP] = {
    0,1,2, 0,1,2,  3,4,5,6, 3,4,5,6,  7,8,9, 7,8,9,
    10,11,12,13, 10,11,12,13,  14,15, 14,15,
    16,17,18,19, 16,17,18,19,  20,21,22, 20,21,22,
    23,24,25,26, 23,24,25,26,  27,28, 27,28};
__constant__ unsigned char sside[NSTEP] = {
    0,0,0, 1,1,1,  0,0,0,0, 1,1,1,1,  0,0,0, 1,1,1,
    0,0,0,0, 1,1,1,1,  0,0, 1,1,
    0,0,0,0, 1,1,1,1,  0,0,0, 1,1,1,
    0,0,0,0, 1,1,1,1,  0,0, 1,1};
// bit0 = zero this side's accumulator first; bit1 = dot after this step
__constant__ unsigned char sflag[NSTEP] = {
    1,0,0, 1,0,2,  1,0,0,0, 1,0,0,2,  1,0,0, 1,0,2,
    1,0,0,0, 1,0,0,2,  1,0, 1,2,
    1,0,0,0, 1,0,0,2,  1,0,0, 1,0,2,
    1,0,0,0, 1,0,0,2,  1,0, 1,2};

// ---------------------------------------------------------------------------
// Scratch
// ---------------------------------------------------------------------------
__device__ float    g_pre[NE * HEADS];
__device__ unsigned g_nmax[NNODES * HEADS];
__device__ float    g_nsum[NNODES * HEADS];
// prepped B^T: [29 terms][2 splits][128 n][64 k] bf16, sign folded
__device__ __align__(16) __nv_bfloat16 g_prepQ[29 * 2 * 8192];
__device__ __align__(16) __nv_bfloat16 g_prepK[29 * 2 * 8192];

// ---------------------------------------------------------------------------
// PTX helpers
// ---------------------------------------------------------------------------
__device__ __forceinline__ u32 smem_u32(const void* p) {
    u32 a;
    asm("{ .reg .u64 t; cvta.to.shared.u64 t, %1; cvt.u32.u64 %0, t; }"
        : "=r"(a) : "l"(p));
    return a;
}
__device__ __forceinline__ void ldsm4(u32 addr, u32* r) {
    asm volatile("ldmatrix.sync.aligned.m8n8.x4.shared.b16 {%0,%1,%2,%3}, [%4];"
                 : "=r"(r[0]), "=r"(r[1]), "=r"(r[2]), "=r"(r[3]) : "r"(addr));
}
__device__ __forceinline__ void mma16816(float* d, const u32* a, u32 b0, u32 b1) {
    asm volatile(
        "mma.sync.aligned.m16n8k16.row.col.f32.bf16.bf16.f32 "
        "{%0,%1,%2,%3}, {%4,%5,%6,%7}, {%8,%9}, {%0,%1,%2,%3};"
        : "+f"(d[0]), "+f"(d[1]), "+f"(d[2]), "+f"(d[3])
        : "r"(a[0]), "r"(a[1]), "r"(a[2]), "r"(a[3]), "r"(b0), "r"(b1));
}
__device__ __forceinline__ void cp16z(u32 dst, const void* src, u32 bytes) {
    asm volatile("cp.async.cg.shared.global [%0], [%1], 16, %2;"
                 :: "r"(dst), "l"(__cvta_generic_to_global(src)), "r"(bytes)
                 : "memory");
}
__device__ __forceinline__ void cp16(u32 dst, const void* src) {
    asm volatile("cp.async.cg.shared.global [%0], [%1], 16;"
                 :: "r"(dst), "l"(__cvta_generic_to_global(src)) : "memory");
}
// split two floats into packed bf16 hi pair + lo pair
__device__ __forceinline__ void split2(float x, float y, u32& hi, u32& lo) {
    __nv_bfloat162 h2 = __floats2bfloat162_rn(x, y);
    u32 hu = *reinterpret_cast<u32*>(&h2);
    float xh = __uint_as_float(hu << 16);
    float yh = __uint_as_float(hu & 0xffff0000u);
    __nv_bfloat162 l2 = __floats2bfloat162_rn(x - xh, y - yh);
    hi = hu;
    lo = *reinterpret_cast<u32*>(&l2);
}

// ---------------------------------------------------------------------------
// Prep: split W into bf16 hi/lo, transpose to B^T[n][k], fold sign.
// ---------------------------------------------------------------------------
__global__ void prep_kernel(const float* __restrict__ Wq,
                            const float* __restrict__ Wk)
{
    int idx = blockIdx.x * blockDim.x + threadIdx.x;
    if (idx >= 29 * 8192) return;
    int t = idx >> 13;
    int r = idx & 8191;
    int d = r >> 7;          // k 0..63
    int c = r & 127;         // n 0..127
    float s = c_sgn[t];
    size_t src = (size_t)c_w[t] * 8192 + (size_t)d * 128 + c;
    size_t dhi = (size_t)t * 16384 + (size_t)c * 64 + d;

    float vq = s * Wq[src];
    __nv_bfloat16 qh = __float2bfloat16(vq);
    g_prepQ[dhi]        = qh;
    g_prepQ[dhi + 8192] = __float2bfloat16(vq - __bfloat162float(qh));

    float vk = s * Wk[src];
    __nv_bfloat16 kh = __float2bfloat16(vk);
    g_prepK[dhi]        = kh;
    g_prepK[dhi + 8192] = __float2bfloat16(vk - __bfloat162float(kh));
}

// ---------------------------------------------------------------------------
// Per-term MMA: warp tile 32(M) x 32(N). A frags from raw fp32 smem (LDS.64 +
// inline hi/lo split); B via ldsm from prepped bf16 smem. bf16x3 = 3 passes.
// ---------------------------------------------------------------------------
__device__ __forceinline__ void term_mma(float (&acc)[2][4][4],
                                         const float* __restrict__ rawW,
                                         u32 bHi, u32 bLo, int lane)
{
    const u32 bRow = (u32)((lane & 7) | ((lane & 16) >> 1)) * BSTR
                   + (u32)((lane >> 3) & 1) * 16u;
    #pragma unroll
    for (int ks = 0; ks < 4; ++ks) {
        const float* rp = rawW + ks * 16;
        float2 x00 = *(const float2*)(rp);
        float2 x10 = *(const float2*)(rp + 8 * RSTR);
        float2 x01 = *(const float2*)(rp + 8);
        float2 x11 = *(const float2*)(rp + 8 * RSTR + 8);
        float2 x20 = *(const float2*)(rp + 16 * RSTR);
        float2 x30 = *(const float2*)(rp + 24 * RSTR);
        float2 x21 = *(const float2*)(rp + 16 * RSTR + 8);
        float2 x31 = *(const float2*)(rp + 24 * RSTR + 8);

        u32 ah0[4], al0[4], ah1[4], al1[4];
        split2(x00.x, x00.y, ah0[0], al0[0]);
        split2(x10.x, x10.y, ah0[1], al0[1]);
        split2(x01.x, x01.y, ah0[2], al0[2]);
        split2(x11.x, x11.y, ah0[3], al0[3]);
        split2(x20.x, x20.y, ah1[0], al1[0]);
        split2(x30.x, x30.y, ah1[1], al1[1]);
        split2(x21.x, x21.y, ah1[2], al1[2]);
        split2(x31.x, x31.y, ah1[3], al1[3]);

        const u32 kb = (u32)ks * 32u;
        #pragma unroll
        for (int np = 0; np < 2; ++np) {
            const u32 bo = bRow + (u32)np * (16u * BSTR) + kb;
            u32 bh[4], bl[4];
            ldsm4(bHi + bo, bh);
            mma16816(acc[0][np*2],   ah0, bh[0], bh[1]);
            mma16816(acc[0][np*2+1], ah0, bh[2], bh[3]);
            mma16816(acc[1][np*2],   ah1, bh[0], bh[1]);
            mma16816(acc[1][np*2+1], ah1, bh[2], bh[3]);
            mma16816(acc[0][np*2],   al0, bh[0], bh[1]);
            mma16816(acc[0][np*2+1], al0, bh[2], bh[3]);
            mma16816(acc[1][np*2],   al1, bh[0], bh[1]);
            mma16816(acc[1][np*2+1], al1, bh[2], bh[3]);
            ldsm4(bLo + bo, bl);
            mma16816(acc[0][np*2],   ah0, bl[0], bl[1]);
            mma16816(acc[0][np*2+1], ah0, bl[2], bl[3]);
            mma16816(acc[1][np*2],   ah1, bl[0], bl[1]);
            mma16816(acc[1][np*2+1], ah1, bl[2], bl[3]);
        }
    }
}

// ---------------------------------------------------------------------------
// Main kernel: 512 threads = 16 warps (4 M-groups x 4 N-groups), warp 32x32.
// Triple-buffered staging, ONE barrier per step.
// ---------------------------------------------------------------------------
__global__ void __launch_bounds__(THREADS, 1)
pre_kernel(const float* __restrict__ xq, const float* __restrict__ xk)
{
    extern __shared__ char smem[];
    const u32 sb   = smem_u32(smem);
    const int tid  = threadIdx.x;
    const int lane = tid & 31;
    const int wid  = tid >> 5;
    const int e0   = blockIdx.x * MT;
    const int m0   = (wid >> 2) * 32;     // warp row base (4 groups)
    const int gn   = wid & 3;             // warp col group (32 cols each)

    const int row  = tid >> 4;            // staging A row (0..31, +32*it)
    const int c4   = tid & 15;            // 16B chunk in row

    // stage one step's A (raw fp32) + B (bf16 hi/lo) into buf s%3
    auto issue = [&](int s) {
        const int  t    = stt[s];
        const u32  bufb = sb + (u32)(s % 3) * BUFSZ;
        // A raw: 128 rows x 256B used (stride 288B), zero-fill OOB rows
        const float* __restrict__ x = sside[s] ? xk : xq;
        const float* abase = x + (size_t)e0 * XDIM + c_i[t] * 64;
        const u32 rdst = bufb + OFF_RAW + (u32)row * (RSTR * 4) + (u32)c4 * 16u;
        #pragma unroll
        for (int it = 0; it < 4; ++it) {
            int rr = row + it * 32;
            u32 ok = (e0 + rr < NE) ? 16u : 0u;
            const float* src = ok ? (abase + (size_t)rr * XDIM + (c4 << 2)) : abase;
            cp16z(rdst + (u32)it * (32u * RSTR * 4), src, ok);
        }
        // B: prepped bf16 hi/lo
        const __nv_bfloat16* bb = (sside[s] ? g_prepK : g_prepQ)
                                + (size_t)t * 16384;
        #pragma unroll
        for (int it = 0; it < 4; ++it) {
            int idx = tid + it * THREADS;          // 0..2047
            int split = idx >> 10;
            int rem   = idx & 1023;
            int r     = rem >> 3;
            int c16   = rem & 7;
            cp16(bufb + (u32)split * 18432u + (u32)r * BSTR + (u32)c16 * 16u,
                 bb + (size_t)split * 8192 + (size_t)r * 64 + (c16 << 3));
        }
        asm volatile("cp.async.commit_group;" ::: "memory");
    };

    float qacc[2][4][4], kacc[2][4][4], preacc[2][2][2];
    #pragma unroll
    for (int a = 0; a < 2; ++a)
        #pragma unroll
        for (int b = 0; b < 2; ++b) { preacc[a][b][0] = 0.f; preacc[a][b][1] = 0.f; }

    // prologue: stage steps 0 and 1
    issue(0);
    issue(1);
    asm volatile("cp.async.wait_group 1;" ::: "memory");
    __syncthreads();

    for (int s = 0; s < NSTEP; ++s) {
        // refill the buffer freed at step s-1 (distinct from bufs s, s+1)
        if (s + 2 < NSTEP) issue(s + 2);

        const u32 bufb = sb + (u32)(s % 3) * BUFSZ;
        const float* rawW = (const float*)(smem + (s % 3) * BUFSZ + OFF_RAW)
                          + (size_t)(m0 + (lane >> 2)) * RSTR + (lane & 3) * 2;
        const u32 bHi = bufb + (u32)(gn * 32) * BSTR;
        const u32 bLo = bHi + 18432u;
        const int fl = sflag[s];

        if (sside[s] == 0) {
            if (fl & 1) {
                #pragma unroll
                for (int i = 0; i < 2; ++i)
                    #pragma unroll
                    for (int j = 0; j < 4; ++j)
                        #pragma unroll
                        for (int r = 0; r < 4; ++r) qacc[i][j][r] = 0.f;
            }
            term_mma(qacc, rawW, bHi, bLo, lane);
        } else {
            if (fl & 1) {
                #pragma unroll
                for (int i = 0; i < 2; ++i)
                    #pragma unroll
                    for (int j = 0; j < 4; ++j)
                        #pragma unroll
                        for (int r = 0; r < 4; ++r) kacc[i][j][r] = 0.f;
            }
            term_mma(kacc, rawW, bHi, bLo, lane);

            if (fl & 2) {   // order finished: per-head dot, register-only
                #pragma unroll
                for (int mt = 0; mt < 2; ++mt)
                    #pragma unroll
                    for (int hl = 0; hl < 2; ++hl) {
                        int nt0 = hl * 2, nt1 = nt0 + 1;
                        preacc[hl][mt][0] +=
                            qacc[mt][nt0][0] * kacc[mt][nt0][0] +
                            qacc[mt][nt0][1] * kacc[mt][nt0][1] +
                            qacc[mt][nt1][0] * kacc[mt][nt1][0] +
                            qacc[mt][nt1][1] * kacc[mt][nt1][1];
                        preacc[hl][mt][1] +=
                            qacc[mt][nt0][2] * kacc[mt][nt0][2] +
                            qacc[mt][nt0][3] * kacc[mt][nt0][3] +
                            qacc[mt][nt1][2] * kacc[mt][nt1][2] +
                            qacc[mt][nt1][3] * kacc[mt][nt1][3];
                    }
            }
        }

        // single barrier per step: make buf s+1 visible everywhere and
        // guarantee all warps are done reading buf s%3 before its reuse.
        if (s + 2 < NSTEP) {
            asm volatile("cp.async.wait_group 1;" ::: "memory");
            __syncthreads();
        } else if (s + 1 < NSTEP) {
            asm volatile("cp.async.wait_group 0;" ::: "memory");
            __syncthreads();
        }
    }

    // reduce across the 4 lanes sharing a row, store
    #pragma unroll
    for (int hl = 0; hl < 2; ++hl)
        #pragma unroll
        for (int mt = 0; mt < 2; ++mt)
            #pragma unroll
            for (int half = 0; half < 2; ++half) {
                float v = preacc[hl][mt][half];
                v += __shfl_xor_sync(0xffffffffu, v, 1);
                v += __shfl_xor_sync(0xffffffffu, v, 2);
                int rr = e0 + m0 + mt * 16 + half * 8 + (lane >> 2);
                if ((lane & 3) == 0 && rr < NE)
                    g_pre[rr * HEADS + gn * 2 + hl] = v * 0.25f;
            }
}

// ---------------------------------------------------------------------------
// Segment softmax (unchanged, passing since round 1)
// ---------------------------------------------------------------------------
__device__ __forceinline__ unsigned enc_f(float f) {
    unsigned u = __float_as_uint(f);
    return (u & 0x80000000u) ? ~u : (u | 0x80000000u);
}
__device__ __forceinline__ float dec_f(unsigned u) {
    return (u & 0x80000000u) ? __uint_as_float(u ^ 0x80000000u)
                             : __uint_as_float(~u);
}
__global__ void init_kernel() {
    int i = blockIdx.x * blockDim.x + threadIdx.x;
    if (i < NNODES * HEADS) { g_nmax[i] = 0u; g_nsum[i] = 0.0f; }
}
__global__ void max_kernel(const int* __restrict__ index) {
    int i = blockIdx.x * blockDim.x + threadIdx.x;
    if (i >= NE * HEADS) return;
    int e = i >> 3, h = i & 7;
    atomicMax(&g_nmax[index[e] * HEADS + h], enc_f(g_pre[i]));
}
__global__ void ex_kernel(const int* __restrict__ index, float* __restrict__ out) {
    int i = blockIdx.x * blockDim.x + threadIdx.x;
    if (i >= NE * HEADS) return;
    int e = i >> 3, h = i & 7;
    int n = index[e] * HEADS + h;
    float ex = expf(g_pre[i] - dec_f(g_nmax[n]));
    out[i] = ex;
    atomicAdd(&g_nsum[n], ex);
}
__global__ void div_kernel(const int* __restrict__ index, float* __restrict__ out) {
    int i = blockIdx.x * blockDim.x + threadIdx.x;
    if (i >= NE * HEADS) return;
    int e = i >> 3, h = i & 7;
    out[i] = out[i] / (g_nsum[index[e] * HEADS + h] + 1e-16f);
}

// ---------------------------------------------------------------------------
extern "C" void kernel_launch(void* const* d_in, const int* in_sizes, int n_in,
                              void* d_out, int out_size)
{
    const float* xq    = (const float*)d_in[0];
    const float* xk    = (const float*)d_in[1];
    const float* Wq    = (const float*)d_in[2];
    const float* Wk    = (const float*)d_in[3];
    const int*   index = (const int*)d_in[4];
    float*       out   = (float*)d_out;

    cudaFuncSetAttribute(pre_kernel,
                         cudaFuncAttributeMaxDynamicSharedMemorySize, SMEM_TOTAL);

    const int T = 256;
    // init launched twice (idempotent): keeps pre_kernel in the 4th launch
    // slot, which is the one ncu captures.
    prep_kernel<<<(29 * 8192 + 255) / 256, 256>>>(Wq, Wk);
    init_kernel<<<(NNODES * HEADS + T - 1) / T, T>>>();
    init_kernel<<<(NNODES * HEADS + T - 1) / T, T>>>();
    pre_kernel<<<NGRID, THREADS, SMEM_TOTAL>>>(xq, xk);

    max_kernel <<<(NE * HEADS + T - 1) / T, T>>>(index);
    ex_kernel  <<<(NE * HEADS + T - 1) / T, T>>>(index, out);
    div_kernel <<<(NE * HEADS + T - 1) / T, T>>>(index, out);
}

// round 7
// speedup vs baseline: 1.0394x; 1.0394x over previous
#include <cuda_runtime.h>
#include <cuda_bf16.h>

// ---------------------------------------------------------------------------
// Static problem shape
// ---------------------------------------------------------------------------
#define NE      100000
#define NNODES  10000
#define HEADS   8
#define XDIM    576
#define MT      64                        // edges per CTA
#define NGRID   ((NE + MT - 1) / MT)      // 1563
#define THREADS 256
#define NSTEP   58

#define BSTR    144                       // B bf16 tile row stride (bytes)
#define RSTR    72                        // raw A row stride (floats) = 288B
// per-CTA smem: 2 buffers, each: B(hi 18432 + lo 18432) + raw A (64*288=18432)
#define OFF_RAW 36864u
#define BUFSZ   55296u
#define SMEM_TOTAL (2 * 55296)            // 110592 per CTA -> 2 CTAs/SM

typedef unsigned int u32;

// ---------------------------------------------------------------------------
// SO(2) path tables (validated rounds 1-6)
// ---------------------------------------------------------------------------
__constant__ int   c_i[29] = {0,2,6,  3,1,7,5,  0,2,6,  3,7,1,5,  8,4,
                              3,1,7,5,  0,2,6,  3,7,1,5,  8,4};
__constant__ int   c_w[29] = {0,3,6,  10,9,14,13,  1,4,7,  9,13,10,14,  18,17,
                              12,11,16,15,  2,5,8,  11,15,12,16,  17,18};
__constant__ float c_sgn[29] = {1,1,1,  1,1,1,1,  1,1,1,  1,1,-1,-1,  1,1,
                                1,1,1,1,  1,1,1,  1,1,-1,-1,  1,-1};

__constant__ unsigned char stt[NSTEP] = {
    0,1,2, 0,1,2,  3,4,5,6, 3,4,5,6,  7,8,9, 7,8,9,
    10,11,12,13, 10,11,12,13,  14,15, 14,15,
    16,17,18,19, 16,17,18,19,  20,21,22, 20,21,22,
    23,24,25,26, 23,24,25,26,  27,28, 27,28};
__constant__ unsigned char sside[NSTEP] = {
    0,0,0, 1,1,1,  0,0,0,0, 1,1,1,1,  0,0,0, 1,1,1,
    0,0,0,0, 1,1,1,1,  0,0, 1,1,
    0,0,0,0, 1,1,1,1,  0,0,0, 1,1,1,
    0,0,0,0, 1,1,1,1,  0,0, 1,1};
// bit0 = zero this side's accumulator first; bit1 = dot after this step
__constant__ unsigned char sflag[NSTEP] = {
    1,0,0, 1,0,2,  1,0,0,0, 1,0,0,2,  1,0,0, 1,0,2,
    1,0,0,0, 1,0,0,2,  1,0, 1,2,
    1,0,0,0, 1,0,0,2,  1,0,0, 1,0,2,
    1,0,0,0, 1,0,0,2,  1,0, 1,2};

// ---------------------------------------------------------------------------
// Scratch
// ---------------------------------------------------------------------------
__device__ float    g_pre[NE * HEADS];
__device__ unsigned g_nmax[NNODES * HEADS];
__device__ float    g_nsum[NNODES * HEADS];
// prepped B^T: [29 terms][2 splits][128 n][64 k] bf16, sign folded
__device__ __align__(16) __nv_bfloat16 g_prepQ[29 * 2 * 8192];
__device__ __align__(16) __nv_bfloat16 g_prepK[29 * 2 * 8192];

// ---------------------------------------------------------------------------
// PTX helpers
// ---------------------------------------------------------------------------
__device__ __forceinline__ u32 smem_u32(const void* p) {
    u32 a;
    asm("{ .reg .u64 t; cvta.to.shared.u64 t, %1; cvt.u32.u64 %0, t; }"
        : "=r"(a) : "l"(p));
    return a;
}
__device__ __forceinline__ void ldsm4(u32 addr, u32* r) {
    asm volatile("ldmatrix.sync.aligned.m8n8.x4.shared.b16 {%0,%1,%2,%3}, [%4];"
                 : "=r"(r[0]), "=r"(r[1]), "=r"(r[2]), "=r"(r[3]) : "r"(addr));
}
__device__ __forceinline__ void mma16816(float* d, const u32* a, u32 b0, u32 b1) {
    asm volatile(
        "mma.sync.aligned.m16n8k16.row.col.f32.bf16.bf16.f32 "
        "{%0,%1,%2,%3}, {%4,%5,%6,%7}, {%8,%9}, {%0,%1,%2,%3};"
        : "+f"(d[0]), "+f"(d[1]), "+f"(d[2]), "+f"(d[3])
        : "r"(a[0]), "r"(a[1]), "r"(a[2]), "r"(a[3]), "r"(b0), "r"(b1));
}
__device__ __forceinline__ void cp16z(u32 dst, const void* src, u32 bytes) {
    asm volatile("cp.async.cg.shared.global [%0], [%1], 16, %2;"
                 :: "r"(dst), "l"(__cvta_generic_to_global(src)), "r"(bytes)
                 : "memory");
}
__device__ __forceinline__ void cp16(u32 dst, const void* src) {
    asm volatile("cp.async.cg.shared.global [%0], [%1], 16;"
                 :: "r"(dst), "l"(__cvta_generic_to_global(src)) : "memory");
}
// split two floats into packed bf16 hi pair + lo pair
__device__ __forceinline__ void split2(float x, float y, u32& hi, u32& lo) {
    __nv_bfloat162 h2 = __floats2bfloat162_rn(x, y);
    u32 hu = *reinterpret_cast<u32*>(&h2);
    float xh = __uint_as_float(hu << 16);
    float yh = __uint_as_float(hu & 0xffff0000u);
    __nv_bfloat162 l2 = __floats2bfloat162_rn(x - xh, y - yh);
    hi = hu;
    lo = *reinterpret_cast<u32*>(&l2);
}

// ---------------------------------------------------------------------------
// Prep: split W into bf16 hi/lo, transpose to B^T[n][k], fold sign.
// ---------------------------------------------------------------------------
__global__ void prep_kernel(const float* __restrict__ Wq,
                            const float* __restrict__ Wk)
{
    int idx = blockIdx.x * blockDim.x + threadIdx.x;
    if (idx >= 29 * 8192) return;
    int t = idx >> 13;
    int r = idx & 8191;
    int d = r >> 7;          // k 0..63
    int c = r & 127;         // n 0..127
    float s = c_sgn[t];
    size_t src = (size_t)c_w[t] * 8192 + (size_t)d * 128 + c;
    size_t dhi = (size_t)t * 16384 + (size_t)c * 64 + d;

    float vq = s * Wq[src];
    __nv_bfloat16 qh = __float2bfloat16(vq);
    g_prepQ[dhi]        = qh;
    g_prepQ[dhi + 8192] = __float2bfloat16(vq - __bfloat162float(qh));

    float vk = s * Wk[src];
    __nv_bfloat16 kh = __float2bfloat16(vk);
    g_prepK[dhi]        = kh;
    g_prepK[dhi + 8192] = __float2bfloat16(vk - __bfloat162float(kh));
}

// ---------------------------------------------------------------------------
// Per-term MMA: warp tile 32(M) x 32(N). A frags from raw fp32 smem (LDS.64 +
// inline hi/lo split); B via ldsm from prepped bf16 smem. bf16x3 = 3 passes.
// (Identical math to round 6 — validated.)
// ---------------------------------------------------------------------------
__device__ __forceinline__ void term_mma(float (&acc)[2][4][4],
                                         const float* __restrict__ rawW,
                                         u32 bHi, u32 bLo, int lane)
{
    const u32 bRow = (u32)((lane & 7) | ((lane & 16) >> 1)) * BSTR
                   + (u32)((lane >> 3) & 1) * 16u;
    #pragma unroll
    for (int ks = 0; ks < 4; ++ks) {
        const float* rp = rawW + ks * 16;
        float2 x00 = *(const float2*)(rp);
        float2 x10 = *(const float2*)(rp + 8 * RSTR);
        float2 x01 = *(const float2*)(rp + 8);
        float2 x11 = *(const float2*)(rp + 8 * RSTR + 8);
        float2 x20 = *(const float2*)(rp + 16 * RSTR);
        float2 x30 = *(const float2*)(rp + 24 * RSTR);
        float2 x21 = *(const float2*)(rp + 16 * RSTR + 8);
        float2 x31 = *(const float2*)(rp + 24 * RSTR + 8);

        u32 ah0[4], al0[4], ah1[4], al1[4];
        split2(x00.x, x00.y, ah0[0], al0[0]);
        split2(x10.x, x10.y, ah0[1], al0[1]);
        split2(x01.x, x01.y, ah0[2], al0[2]);
        split2(x11.x, x11.y, ah0[3], al0[3]);
        split2(x20.x, x20.y, ah1[0], al1[0]);
        split2(x30.x, x30.y, ah1[1], al1[1]);
        split2(x21.x, x21.y, ah1[2], al1[2]);
        split2(x31.x, x31.y, ah1[3], al1[3]);

        const u32 kb = (u32)ks * 32u;
        #pragma unroll
        for (int np = 0; np < 2; ++np) {
            const u32 bo = bRow + (u32)np * (16u * BSTR) + kb;
            u32 bh[4], bl[4];
            ldsm4(bHi + bo, bh);
            mma16816(acc[0][np*2],   ah0, bh[0], bh[1]);
            mma16816(acc[0][np*2+1], ah0, bh[2], bh[3]);
            mma16816(acc[1][np*2],   ah1, bh[0], bh[1]);
            mma16816(acc[1][np*2+1], ah1, bh[2], bh[3]);
            mma16816(acc[0][np*2],   al0, bh[0], bh[1]);
            mma16816(acc[0][np*2+1], al0, bh[2], bh[3]);
            mma16816(acc[1][np*2],   al1, bh[0], bh[1]);
            mma16816(acc[1][np*2+1], al1, bh[2], bh[3]);
            ldsm4(bLo + bo, bl);
            mma16816(acc[0][np*2],   ah0, bl[0], bl[1]);
            mma16816(acc[0][np*2+1], ah0, bl[2], bl[3]);
            mma16816(acc[1][np*2],   ah1, bl[0], bl[1]);
            mma16816(acc[1][np*2+1], ah1, bl[2], bl[3]);
        }
    }
}

// ---------------------------------------------------------------------------
// Main kernel: 256 threads = 8 warps (2 M-groups x 4 N-groups), warp 32x32,
// MT=64 edges/CTA -> 2 CTAs per SM (independent barriers cover each other's
// stalls). Double-buffered, ONE barrier per step.
// ---------------------------------------------------------------------------
__global__ void __launch_bounds__(THREADS, 2)
pre_kernel(const float* __restrict__ xq, const float* __restrict__ xk)
{
    extern __shared__ char smem[];
    const u32 sb   = smem_u32(smem);
    const int tid  = threadIdx.x;
    const int lane = tid & 31;
    const int wid  = tid >> 5;
    const int e0   = blockIdx.x * MT;
    const int m0   = (wid >> 2) * 32;     // warp row base (2 groups)
    const int gn   = wid & 3;             // warp col group (32 cols each)

    // stage one step's A (raw fp32, 64 rows x 256B) + B (bf16 hi/lo) -> buf s%2
    auto issue = [&](int s) {
        const int  t    = stt[s];
        const u32  bufb = sb + (u32)(s & 1) * BUFSZ;
        const float* __restrict__ x = sside[s] ? xk : xq;
        const float* abase = x + (size_t)e0 * XDIM + c_i[t] * 64;
        #pragma unroll
        for (int it = 0; it < 4; ++it) {
            int idx = tid + it * THREADS;   // 0..1023
            int rr  = idx >> 4;             // 0..63
            int cc  = idx & 15;
            u32 ok = (e0 + rr < NE) ? 16u : 0u;
            const float* src = ok ? (abase + (size_t)rr * XDIM + (cc << 2)) : abase;
            cp16z(bufb + OFF_RAW + (u32)rr * (RSTR * 4) + (u32)cc * 16u, src, ok);
        }
        const __nv_bfloat16* bb = (sside[s] ? g_prepK : g_prepQ)
                                + (size_t)t * 16384;
        #pragma unroll
        for (int it = 0; it < 8; ++it) {
            int idx = tid + it * THREADS;          // 0..2047
            int split = idx >> 10;
            int rem   = idx & 1023;
            int r     = rem >> 3;
            int c16   = rem & 7;
            cp16(bufb + (u32)split * 18432u + (u32)r * BSTR + (u32)c16 * 16u,
                 bb + (size_t)split * 8192 + (size_t)r * 64 + (c16 << 3));
        }
        asm volatile("cp.async.commit_group;" ::: "memory");
    };

    float qacc[2][4][4], kacc[2][4][4], preacc[2][2][2];
    #pragma unroll
    for (int a = 0; a < 2; ++a)
        #pragma unroll
        for (int b = 0; b < 2; ++b) { preacc[a][b][0] = 0.f; preacc[a][b][1] = 0.f; }

    // prologue: stage steps 0 and 1
    issue(0);
    issue(1);
    asm volatile("cp.async.wait_group 1;" ::: "memory");   // group(0) done
    __syncthreads();

    for (int s = 0; s < NSTEP; ++s) {
        const u32 bufb = sb + (u32)(s & 1) * BUFSZ;
        const float* rawW = (const float*)(smem + (s & 1) * BUFSZ + OFF_RAW)
                          + (size_t)(m0 + (lane >> 2)) * RSTR + (lane & 3) * 2;
        const u32 bHi = bufb + (u32)(gn * 32) * BSTR;
        const u32 bLo = bHi + 18432u;
        const int fl = sflag[s];

        if (sside[s] == 0) {
            if (fl & 1) {
                #pragma unroll
                for (int i = 0; i < 2; ++i)
                    #pragma unroll
                    for (int j = 0; j < 4; ++j)
                        #pragma unroll
                        for (int r = 0; r < 4; ++r) qacc[i][j][r] = 0.f;
            }
            term_mma(qacc, rawW, bHi, bLo, lane);
        } else {
            if (fl & 1) {
                #pragma unroll
                for (int i = 0; i < 2; ++i)
                    #pragma unroll
                    for (int j = 0; j < 4; ++j)
                        #pragma unroll
                        for (int r = 0; r < 4; ++r) kacc[i][j][r] = 0.f;
            }
            term_mma(kacc, rawW, bHi, bLo, lane);

            if (fl & 2) {   // order finished: per-head dot, register-only
                #pragma unroll
                for (int mt = 0; mt < 2; ++mt)
                    #pragma unroll
                    for (int hl = 0; hl < 2; ++hl) {
                        int nt0 = hl * 2, nt1 = nt0 + 1;
                        preacc[hl][mt][0] +=
                            qacc[mt][nt0][0] * kacc[mt][nt0][0] +
                            qacc[mt][nt0][1] * kacc[mt][nt0][1] +
                            qacc[mt][nt1][0] * kacc[mt][nt1][0] +
                            qacc[mt][nt1][1] * kacc[mt][nt1][1];
                        preacc[hl][mt][1] +=
                            qacc[mt][nt0][2] * kacc[mt][nt0][2] +
                            qacc[mt][nt0][3] * kacc[mt][nt0][3] +
                            qacc[mt][nt1][2] * kacc[mt][nt1][2] +
                            qacc[mt][nt1][3] * kacc[mt][nt1][3];
                    }
            }
        }

        // one barrier per step: own group(s+1) already in flight a full step,
        // sync makes it visible to all and frees buf[s&1] for step s+2.
        if (s + 1 < NSTEP) {
            asm volatile("cp.async.wait_group 0;" ::: "memory");
            __syncthreads();
            if (s + 2 < NSTEP) issue(s + 2);
        }
    }

    // reduce across the 4 lanes sharing a row, store
    #pragma unroll
    for (int hl = 0; hl < 2; ++hl)
        #pragma unroll
        for (int mt = 0; mt < 2; ++mt)
            #pragma unroll
            for (int half = 0; half < 2; ++half) {
                float v = preacc[hl][mt][half];
                v += __shfl_xor_sync(0xffffffffu, v, 1);
                v += __shfl_xor_sync(0xffffffffu, v, 2);
                int rr = e0 + m0 + mt * 16 + half * 8 + (lane >> 2);
                if ((lane & 3) == 0 && rr < NE)
                    g_pre[rr * HEADS + gn * 2 + hl] = v * 0.25f;
            }
}

// ---------------------------------------------------------------------------
// Segment softmax (unchanged, passing since round 1)
// ---------------------------------------------------------------------------
__device__ __forceinline__ unsigned enc_f(float f) {
    unsigned u = __float_as_uint(f);
    return (u & 0x80000000u) ? ~u : (u | 0x80000000u);
}
__device__ __forceinline__ float dec_f(unsigned u) {
    return (u & 0x80000000u) ? __uint_as_float(u ^ 0x80000000u)
                             : __uint_as_float(~u);
}
__global__ void init_kernel() {
    int i = blockIdx.x * blockDim.x + threadIdx.x;
    if (i < NNODES * HEADS) { g_nmax[i] = 0u; g_nsum[i] = 0.0f; }
}
__global__ void max_kernel(const int* __restrict__ index) {
    int i = blockIdx.x * blockDim.x + threadIdx.x;
    if (i >= NE * HEADS) return;
    int e = i >> 3, h = i & 7;
    atomicMax(&g_nmax[index[e] * HEADS + h], enc_f(g_pre[i]));
}
__global__ void ex_kernel(const int* __restrict__ index, float* __restrict__ out) {
    int i = blockIdx.x * blockDim.x + threadIdx.x;
    if (i >= NE * HEADS) return;
    int e = i >> 3, h = i & 7;
    int n = index[e] * HEADS + h;
    float ex = expf(g_pre[i] - dec_f(g_nmax[n]));
    out[i] = ex;
    atomicAdd(&g_nsum[n], ex);
}
__global__ void div_kernel(const int* __restrict__ index, float* __restrict__ out) {
    int i = blockIdx.x * blockDim.x + threadIdx.x;
    if (i >= NE * HEADS) return;
    int e = i >> 3, h = i & 7;
    out[i] = out[i] / (g_nsum[index[e] * HEADS + h] + 1e-16f);
}

// ---------------------------------------------------------------------------
extern "C" void kernel_launch(void* const* d_in, const int* in_sizes, int n_in,
                              void* d_out, int out_size)
{
    const float* xq    = (const float*)d_in[0];
    const float* xk    = (const float*)d_in[1];
    const float* Wq    = (const float*)d_in[2];
    const float* Wk    = (const float*)d_in[3];
    const int*   index = (const int*)d_in[4];
    float*       out   = (float*)d_out;

    cudaFuncSetAttribute(pre_kernel,
                         cudaFuncAttributeMaxDynamicSharedMemorySize, SMEM_TOTAL);

    const int T = 256;
    // init launched twice (idempotent): keeps pre_kernel in the 4th launch
    // slot, which is the one ncu captures.
    prep_kernel<<<(29 * 8192 + 255) / 256, 256>>>(Wq, Wk);
    init_kernel<<<(NNODES * HEADS + T - 1) / T, T>>>();
    init_kernel<<<(NNODES * HEADS + T - 1) / T, T>>>();
    pre_kernel<<<NGRID, THREADS, SMEM_TOTAL>>>(xq, xk);

    max_kernel <<<(NE * HEADS + T - 1) / T, T>>>(index);
    ex_kernel  <<<(NE * HEADS + T - 1) / T, T>>>(index, out);
    div_kernel <<<(NE * HEADS + T - 1) / T, T>>>(index, out);
}

// round 8
// speedup vs baseline: 1.0856x; 1.0444x over previous
#include <cuda_runtime.h>
#include <cuda_bf16.h>

// ---------------------------------------------------------------------------
// Static problem shape
// ---------------------------------------------------------------------------
#define NE      100000
#define NNODES  10000
#define HEADS   8
#define XDIM    576
#define MT      64                        // edges per CTA
#define NGRID   ((NE + MT - 1) / MT)      // 1563
#define THREADS 256
#define NSTEP   58

#define BSTR    144                       // tile row stride (bytes), A and B
// per-CTA smem buffer: [Bhi 18432][Blo 18432][Ahi 9216][Alo 9216] = 55296
#define OFF_AHI 36864u
#define OFF_ALO 46080u
#define BUFSZ   55296u
#define SMEM_TOTAL (2 * 55296)            // 110592 -> 2 CTAs/SM

typedef unsigned int u32;

// ---------------------------------------------------------------------------
// SO(2) path tables (validated rounds 1-7)
// ---------------------------------------------------------------------------
__constant__ int   c_i[29] = {0,2,6,  3,1,7,5,  0,2,6,  3,7,1,5,  8,4,
                              3,1,7,5,  0,2,6,  3,7,1,5,  8,4};
__constant__ int   c_w[29] = {0,3,6,  10,9,14,13,  1,4,7,  9,13,10,14,  18,17,
                              12,11,16,15,  2,5,8,  11,15,12,16,  17,18};
__constant__ float c_sgn[29] = {1,1,1,  1,1,1,1,  1,1,1,  1,1,-1,-1,  1,1,
                                1,1,1,1,  1,1,1,  1,1,-1,-1,  1,-1};

__constant__ unsigned char stt[NSTEP] = {
    0,1,2, 0,1,2,  3,4,5,6, 3,4,5,6,  7,8,9, 7,8,9,
    10,11,12,13, 10,11,12,13,  14,15, 14,15,
    16,17,18,19, 16,17,18,19,  20,21,22, 20,21,22,
    23,24,25,26, 23,24,25,26,  27,28, 27,28};
__constant__ unsigned char sside[NSTEP] = {
    0,0,0, 1,1,1,  0,0,0,0, 1,1,1,1,  0,0,0, 1,1,1,
    0,0,0,0, 1,1,1,1,  0,0, 1,1,
    0,0,0,0, 1,1,1,1,  0,0,0, 1,1,1,
    0,0,0,0, 1,1,1,1,  0,0, 1,1};
// bit0 = zero this side's accumulator first; bit1 = dot after this step
__constant__ unsigned char sflag[NSTEP] = {
    1,0,0, 1,0,2,  1,0,0,0, 1,0,0,2,  1,0,0, 1,0,2,
    1,0,0,0, 1,0,0,2,  1,0, 1,2,
    1,0,0,0, 1,0,0,2,  1,0,0, 1,0,2,
    1,0,0,0, 1,0,0,2,  1,0, 1,2};

// ---------------------------------------------------------------------------
// Scratch
// ---------------------------------------------------------------------------
__device__ float    g_pre[NE * HEADS];
__device__ unsigned g_nmax[NNODES * HEADS];
__device__ float    g_nsum[NNODES * HEADS];
// prepped B^T: [29 terms][2 splits][128 n][64 k] bf16, sign folded
__device__ __align__(16) __nv_bfloat16 g_prepQ[29 * 2 * 8192];
__device__ __align__(16) __nv_bfloat16 g_prepK[29 * 2 * 8192];

// ---------------------------------------------------------------------------
// PTX helpers
// ---------------------------------------------------------------------------
__device__ __forceinline__ u32 smem_u32(const void* p) {
    u32 a;
    asm("{ .reg .u64 t; cvta.to.shared.u64 t, %1; cvt.u32.u64 %0, t; }"
        : "=r"(a) : "l"(p));
    return a;
}
__device__ __forceinline__ void ldsm4(u32 addr, u32* r) {
    asm volatile("ldmatrix.sync.aligned.m8n8.x4.shared.b16 {%0,%1,%2,%3}, [%4];"
                 : "=r"(r[0]), "=r"(r[1]), "=r"(r[2]), "=r"(r[3]) : "r"(addr));
}
__device__ __forceinline__ void mma16816(float* d, const u32* a, u32 b0, u32 b1) {
    asm volatile(
        "mma.sync.aligned.m16n8k16.row.col.f32.bf16.bf16.f32 "
        "{%0,%1,%2,%3}, {%4,%5,%6,%7}, {%8,%9}, {%0,%1,%2,%3};"
        : "+f"(d[0]), "+f"(d[1]), "+f"(d[2]), "+f"(d[3])
        : "r"(a[0]), "r"(a[1]), "r"(a[2]), "r"(a[3]), "r"(b0), "r"(b1));
}
__device__ __forceinline__ void cp16(u32 dst, const void* src) {
    asm volatile("cp.async.cg.shared.global [%0], [%1], 16;"
                 :: "r"(dst), "l"(__cvta_generic_to_global(src)) : "memory");
}
// split two floats into packed bf16 hi pair + lo pair
__device__ __forceinline__ void split2(float x, float y, u32& hi, u32& lo) {
    __nv_bfloat162 h2 = __floats2bfloat162_rn(x, y);
    u32 hu = *reinterpret_cast<u32*>(&h2);
    float xh = __uint_as_float(hu << 16);
    float yh = __uint_as_float(hu & 0xffff0000u);
    __nv_bfloat162 l2 = __floats2bfloat162_rn(x - xh, y - yh);
    hi = hu;
    lo = *reinterpret_cast<u32*>(&l2);
}

// ---------------------------------------------------------------------------
// Prep: split W into bf16 hi/lo, transpose to B^T[n][k], fold sign.
// ---------------------------------------------------------------------------
__global__ void prep_kernel(const float* __restrict__ Wq,
                            const float* __restrict__ Wk)
{
    int idx = blockIdx.x * blockDim.x + threadIdx.x;
    if (idx >= 29 * 8192) return;
    int t = idx >> 13;
    int r = idx & 8191;
    int d = r >> 7;          // k 0..63
    int c = r & 127;         // n 0..127
    float s = c_sgn[t];
    size_t src = (size_t)c_w[t] * 8192 + (size_t)d * 128 + c;
    size_t dhi = (size_t)t * 16384 + (size_t)c * 64 + d;

    float vq = s * Wq[src];
    __nv_bfloat16 qh = __float2bfloat16(vq);
    g_prepQ[dhi]        = qh;
    g_prepQ[dhi + 8192] = __float2bfloat16(vq - __bfloat162float(qh));

    float vk = s * Wk[src];
    __nv_bfloat16 kh = __float2bfloat16(vk);
    g_prepK[dhi]        = kh;
    g_prepK[dhi + 8192] = __float2bfloat16(vk - __bfloat162float(kh));
}

// ---------------------------------------------------------------------------
// Per-term MMA: warp tile 32(M) x 32(N). BOTH A and B fragments via ldmatrix
// from pre-split bf16 smem tiles (NO ALU in the compute path). bf16x3.
// A-frag pattern = round-3-validated: (lane&15)*stride + (lane>>4)*16.
// ---------------------------------------------------------------------------
__device__ __forceinline__ void term_mma(float (&acc)[2][4][4],
                                         u32 aHi, u32 aLo,
                                         u32 bHi, u32 bLo, int lane)
{
    const u32 aRow = (u32)(lane & 15) * BSTR + (u32)(lane >> 4) * 16u;
    const u32 bRow = (u32)((lane & 7) | ((lane & 16) >> 1)) * BSTR
                   + (u32)((lane >> 3) & 1) * 16u;
    #pragma unroll
    for (int ks = 0; ks < 4; ++ks) {
        const u32 kb = (u32)ks * 32u;
        u32 ah0[4], ah1[4], al0[4], al1[4];
        ldsm4(aHi + aRow + kb, ah0);
        ldsm4(aHi + aRow + 16u * BSTR + kb, ah1);
        ldsm4(aLo + aRow + kb, al0);
        ldsm4(aLo + aRow + 16u * BSTR + kb, al1);

        #pragma unroll
        for (int np = 0; np < 2; ++np) {
            const u32 bo = bRow + (u32)np * (16u * BSTR) + kb;
            u32 bh[4], bl[4];
            ldsm4(bHi + bo, bh);
            mma16816(acc[0][np*2],   ah0, bh[0], bh[1]);
            mma16816(acc[0][np*2+1], ah0, bh[2], bh[3]);
            mma16816(acc[1][np*2],   ah1, bh[0], bh[1]);
            mma16816(acc[1][np*2+1], ah1, bh[2], bh[3]);
            mma16816(acc[0][np*2],   al0, bh[0], bh[1]);
            mma16816(acc[0][np*2+1], al0, bh[2], bh[3]);
            mma16816(acc[1][np*2],   al1, bh[0], bh[1]);
            mma16816(acc[1][np*2+1], al1, bh[2], bh[3]);
            ldsm4(bLo + bo, bl);
            mma16816(acc[0][np*2],   ah0, bl[0], bl[1]);
            mma16816(acc[0][np*2+1], ah0, bl[2], bl[3]);
            mma16816(acc[1][np*2],   ah1, bl[0], bl[1]);
            mma16816(acc[1][np*2+1], ah1, bl[2], bl[3]);
        }
    }
}

// ---------------------------------------------------------------------------
// Main kernel: 256 threads = 8 warps (2 M x 4 N groups), MT=64, 2 CTAs/SM.
// A: LDG->regs at iter start (latency covered by compute), split+STS after
// the barrier. B: cp.async of pre-split weights. One barrier per step.
// ---------------------------------------------------------------------------
__global__ void __launch_bounds__(THREADS, 2)
pre_kernel(const float* __restrict__ xq, const float* __restrict__ xk)
{
    extern __shared__ char smem[];
    const u32 sb   = smem_u32(smem);
    const int tid  = threadIdx.x;
    const int lane = tid & 31;
    const int wid  = tid >> 5;
    const int e0   = blockIdx.x * MT;
    const int m0   = (wid >> 2) * 32;     // warp row base (2 groups)
    const int gn   = wid & 3;             // warp col group (32 cols each)

    const int arow = tid >> 2;            // staging: A row 0..63
    const int akc  = tid & 3;             // k chunk (16 floats each)

    // A: load this thread's 16 fp32 values for step s into registers
    auto ldgA = [&](int s, float4* rv) {
        const float* __restrict__ x = sside[s] ? xk : xq;
        const bool ok = (e0 + arow < NE);
        const float* p = x + (size_t)(e0 + arow) * XDIM + c_i[stt[s]] * 64 + akc * 16;
        #pragma unroll
        for (int j = 0; j < 4; ++j)
            rv[j] = ok ? *(const float4*)(p + j * 4)
                       : make_float4(0.f, 0.f, 0.f, 0.f);
    };
    // A: split regs -> bf16 hi/lo smem tiles for step s
    auto stsA = [&](int s, const float4* rv) {
        const u32 d = sb + (u32)(s & 1) * BUFSZ + (u32)arow * BSTR + (u32)akc * 32u;
        u32 h[8], l[8];
        #pragma unroll
        for (int j = 0; j < 4; ++j) {
            split2(rv[j].x, rv[j].y, h[2*j],   l[2*j]);
            split2(rv[j].z, rv[j].w, h[2*j+1], l[2*j+1]);
        }
        *(uint4*)(smem + (d - sb) + OFF_AHI)       = make_uint4(h[0], h[1], h[2], h[3]);
        *(uint4*)(smem + (d - sb) + OFF_AHI + 16u) = make_uint4(h[4], h[5], h[6], h[7]);
        *(uint4*)(smem + (d - sb) + OFF_ALO)       = make_uint4(l[0], l[1], l[2], l[3]);
        *(uint4*)(smem + (d - sb) + OFF_ALO + 16u) = make_uint4(l[4], l[5], l[6], l[7]);
    };
    // B: cp.async pre-split weights for step s, then commit the group
    auto cpB = [&](int s) {
        const __nv_bfloat16* bb = (sside[s] ? g_prepK : g_prepQ)
                                + (size_t)stt[s] * 16384;
        const u32 bufb = sb + (u32)(s & 1) * BUFSZ;
        #pragma unroll
        for (int it = 0; it < 8; ++it) {
            int idx = tid + it * THREADS;          // 0..2047
            int split = idx >> 10;
            int rem   = idx & 1023;
            int r     = rem >> 3;
            int c16   = rem & 7;
            cp16(bufb + (u32)split * 18432u + (u32)r * BSTR + (u32)c16 * 16u,
                 bb + (size_t)split * 8192 + (size_t)r * 64 + (c16 << 3));
        }
        asm volatile("cp.async.commit_group;" ::: "memory");
    };

    float qacc[2][4][4], kacc[2][4][4], preacc[2][2][2];
    #pragma unroll
    for (int a = 0; a < 2; ++a)
        #pragma unroll
        for (int b = 0; b < 2; ++b) { preacc[a][b][0] = 0.f; preacc[a][b][1] = 0.f; }

    float4 rv[4];

    // prologue: stage steps 0 and 1
    ldgA(0, rv); stsA(0, rv); cpB(0);
    ldgA(1, rv); stsA(1, rv); cpB(1);
    asm volatile("cp.async.wait_group 1;" ::: "memory");   // B(0) done
    __syncthreads();

    for (int s = 0; s < NSTEP; ++s) {
        if (s + 2 < NSTEP) ldgA(s + 2, rv);    // covered by compute below

        const u32 bufb = sb + (u32)(s & 1) * BUFSZ;
        const u32 aHi  = bufb + OFF_AHI + (u32)m0 * BSTR;
        const u32 aLo  = bufb + OFF_ALO + (u32)m0 * BSTR;
        const u32 bHi  = bufb + (u32)(gn * 32) * BSTR;
        const u32 bLo  = bHi + 18432u;
        const int fl   = sflag[s];

        if (sside[s] == 0) {
            if (fl & 1) {
                #pragma unroll
                for (int i = 0; i < 2; ++i)
                    #pragma unroll
                    for (int j = 0; j < 4; ++j)
                        #pragma unroll
                        for (int r = 0; r < 4; ++r) qacc[i][j][r] = 0.f;
            }
            term_mma(qacc, aHi, aLo, bHi, bLo, lane);
        } else {
            if (fl & 1) {
                #pragma unroll
                for (int i = 0; i < 2; ++i)
                    #pragma unroll
                    for (int j = 0; j < 4; ++j)
                        #pragma unroll
                        for (int r = 0; r < 4; ++r) kacc[i][j][r] = 0.f;
            }
            term_mma(kacc, aHi, aLo, bHi, bLo, lane);

            if (fl & 2) {   // order finished: per-head dot, register-only
                #pragma unroll
                for (int mt = 0; mt < 2; ++mt)
                    #pragma unroll
                    for (int hl = 0; hl < 2; ++hl) {
                        int nt0 = hl * 2, nt1 = nt0 + 1;
                        preacc[hl][mt][0] +=
                            qacc[mt][nt0][0] * kacc[mt][nt0][0] +
                            qacc[mt][nt0][1] * kacc[mt][nt0][1] +
                            qacc[mt][nt1][0] * kacc[mt][nt1][0] +
                            qacc[mt][nt1][1] * kacc[mt][nt1][1];
                        preacc[hl][mt][1] +=
                            qacc[mt][nt0][2] * kacc[mt][nt0][2] +
                            qacc[mt][nt0][3] * kacc[mt][nt0][3] +
                            qacc[mt][nt1][2] * kacc[mt][nt1][2] +
                            qacc[mt][nt1][3] * kacc[mt][nt1][3];
                    }
            }
        }

        if (s + 1 < NSTEP) {
            // only group(s+1) is outstanding here -> wait_group 0 == it
            asm volatile("cp.async.wait_group 0;" ::: "memory");
            __syncthreads();                   // buf[s&1] free, B(s+1) visible
            if (s + 2 < NSTEP) { stsA(s + 2, rv); cpB(s + 2); }
        }
    }

    // reduce across the 4 lanes sharing a row, store
    #pragma unroll
    for (int hl = 0; hl < 2; ++hl)
        #pragma unroll
        for (int mt = 0; mt < 2; ++mt)
            #pragma unroll
            for (int half = 0; half < 2; ++half) {
                float v = preacc[hl][mt][half];
                v += __shfl_xor_sync(0xffffffffu, v, 1);
                v += __shfl_xor_sync(0xffffffffu, v, 2);
                int rr = e0 + m0 + mt * 16 + half * 8 + (lane >> 2);
                if ((lane & 3) == 0 && rr < NE)
                    g_pre[rr * HEADS + gn * 2 + hl] = v * 0.25f;
            }
}

// ---------------------------------------------------------------------------
// Segment softmax (unchanged, passing since round 1)
// ---------------------------------------------------------------------------
__device__ __forceinline__ unsigned enc_f(float f) {
    unsigned u = __float_as_uint(f);
    return (u & 0x80000000u) ? ~u : (u | 0x80000000u);
}
__device__ __forceinline__ float dec_f(unsigned u) {
    return (u & 0x80000000u) ? __uint_as_float(u ^ 0x80000000u)
                             : __uint_as_float(~u);
}
__global__ void init_kernel() {
    int i = blockIdx.x * blockDim.x + threadIdx.x;
    if (i < NNODES * HEADS) { g_nmax[i] = 0u; g_nsum[i] = 0.0f; }
}
__global__ void max_kernel(const int* __restrict__ index) {
    int i = blockIdx.x * blockDim.x + threadIdx.x;
    if (i >= NE * HEADS) return;
    int e = i >> 3, h = i & 7;
    atomicMax(&g_nmax[index[e] * HEADS + h], enc_f(g_pre[i]));
}
__global__ void ex_kernel(const int* __restrict__ index, float* __restrict__ out) {
    int i = blockIdx.x * blockDim.x + threadIdx.x;
    if (i >= NE * HEADS) return;
    int e = i >> 3, h = i & 7;
    int n = index[e] * HEADS + h;
    float ex = expf(g_pre[i] - dec_f(g_nmax[n]));
    out[i] = ex;
    atomicAdd(&g_nsum[n], ex);
}
__global__ void div_kernel(const int* __restrict__ index, float* __restrict__ out) {
    int i = blockIdx.x * blockDim.x + threadIdx.x;
    if (i >= NE * HEADS) return;
    int e = i >> 3, h = i & 7;
    out[i] = out[i] / (g_nsum[index[e] * HEADS + h] + 1e-16f);
}

// ---------------------------------------------------------------------------
extern "C" void kernel_launch(void* const* d_in, const int* in_sizes, int n_in,
                              void* d_out, int out_size)
{
    const float* xq    = (const float*)d_in[0];
    const float* xk    = (const float*)d_in[1];
    const float* Wq    = (const float*)d_in[2];
    const float* Wk    = (const float*)d_in[3];
    const int*   index = (const int*)d_in[4];
    float*       out   = (float*)d_out;

    cudaFuncSetAttribute(pre_kernel,
                         cudaFuncAttributeMaxDynamicSharedMemorySize, SMEM_TOTAL);

    const int T = 256;
    // init launched twice (idempotent): keeps pre_kernel in the 4th launch
    // slot, which is the one ncu captures.
    prep_kernel<<<(29 * 8192 + 255) / 256, 256>>>(Wq, Wk);
    init_kernel<<<(NNODES * HEADS + T - 1) / T, T>>>();
    init_kernel<<<(NNODES * HEADS + T - 1) / T, T>>>();
    pre_kernel<<<NGRID, THREADS, SMEM_TOTAL>>>(xq, xk);

    max_kernel <<<(NE * HEADS + T - 1) / T, T>>>(index);
    ex_kernel  <<<(NE * HEADS + T - 1) / T, T>>>(index, out);
    div_kernel <<<(NE * HEADS + T - 1) / T, T>>>(index, out);
}